// round 4
// baseline (speedup 1.0000x reference)
#include <cuda_runtime.h>
#include <math.h>

// ---------------------------------------------------------------------------
// Problem dims (fixed)
//   D=1024, P=128, B=4096, NS=NT=8192, C=1000
// Inputs (metadata order):
//   0 Ft(1000,1024) 1 Fv(4096,1024) 2 Fvs(8192,1024) 3 Fvt(8192,1024)
//   4 W1(128,1024) 5 b1 6 g1 7 be1 8 m1 9 v1
//   10 W2(128,128) 11 b2 12 g2 13 be2 14 m2 15 v2
//   16 W3(3072,128) 17 b3  18 Wp(1024,1024) 19 bp  20 logit_scale(1)
// Output: logits (4096,1000) fp32
// ---------------------------------------------------------------------------

#define BM 128
#define BN 128
#define BK 16
#define GEMM_THREADS 256

#define MODE_SCALE   0   // C = acc * scale
#define MODE_BNRELU  1   // C = relu((acc + b - m) * rsqrt(v+eps) * g + be)
#define MODE_QKV     2   // scatter acc+b3 to q/k/v (col j -> buf j%3, col j/3)
#define MODE_RESID   3   // C = acc + bias[col] + resid[row,col]
#define MODE_LS      4   // C = acc * exp(*lsp)

// ---------------- scratch (static device memory; no allocations) -----------
__device__ float g_H1[8192 * 128];
__device__ float g_H2[8192 * 128];
__device__ float g_Q [4096 * 1024];
__device__ float g_K [8192 * 1024];
__device__ float g_V [8192 * 1024];
__device__ float g_S [(size_t)4096 * 8192];
__device__ float g_AV[4096 * 1024];
__device__ float g_F [4096 * 1024];
__device__ float g_G [4096 * 1024];

// ---------------- packed f32x2 helpers (sm_103a FFMA2, rt=1 vs 2) ----------
__device__ __forceinline__ unsigned long long pack2(float x, float y) {
    unsigned long long r;
    unsigned lo = __float_as_uint(x), hi = __float_as_uint(y);
    asm("mov.b64 %0, {%1, %2};" : "=l"(r) : "r"(lo), "r"(hi));
    return r;
}
__device__ __forceinline__ float2 unpack2(unsigned long long v) {
    unsigned lo, hi;
    asm("mov.b64 {%0, %1}, %2;" : "=r"(lo), "=r"(hi) : "l"(v));
    return make_float2(__uint_as_float(lo), __uint_as_float(hi));
}
__device__ __forceinline__ void fma2(unsigned long long& d,
                                     unsigned long long a,
                                     unsigned long long b) {
    asm("fma.rn.f32x2 %0, %1, %2, %0;" : "+l"(d) : "l"(a), "l"(b));
}

// ---------------------------------------------------------------------------
// Generic tiled GEMM: C(MxN) = A(MxK) @ op(B)
//   TRANSB=true : B is (N,K) row-major -> C = A @ B^T
//   TRANSB=false: B is (K,N) row-major -> C = A @ B
// M % 128 == 0, K % 16 == 0 guaranteed by the problem; N may be ragged (1000).
// ---------------------------------------------------------------------------
template <bool TRANSB>
__global__ __launch_bounds__(GEMM_THREADS)
void gemm_kernel(const float* __restrict__ A, const float* __restrict__ B,
                 float* __restrict__ C, int M, int N, int K,
                 int mode, float scale,
                 const float* __restrict__ bias,
                 const float* __restrict__ gam, const float* __restrict__ bet,
                 const float* __restrict__ mean, const float* __restrict__ var,
                 const float* __restrict__ resid,
                 const float* __restrict__ lsp,
                 float* __restrict__ qo, float* __restrict__ ko,
                 float* __restrict__ vo)
{
    __shared__ float As[BK][BM];
    __shared__ float Bs[BK][BN + 4];

    const int tid = threadIdx.x;
    const int m0 = blockIdx.y * BM;
    const int n0 = blockIdx.x * BN;
    const int ty = tid >> 4;          // 0..15
    const int tx = tid & 15;          // 0..15

    // loader mapping (row-major 2D tiles, float4)
    const int aRow = tid >> 2;        // 0..63
    const int aCol = (tid & 3) << 2;  // 0,4,8,12
    const int bRowNN = tid >> 5;      // 0..7
    const int bColNN = (tid & 31) << 2;

    unsigned long long acc[8][4];
#pragma unroll
    for (int i = 0; i < 8; ++i)
#pragma unroll
        for (int j = 0; j < 4; ++j) acc[i][j] = 0ull;

    for (int k0 = 0; k0 < K; k0 += BK) {
        // ---- load A tile (transposed into smem: As[k][m]) ----
#pragma unroll
        for (int r = 0; r < 2; ++r) {
            const int m = aRow + r * 64;
            const float4 va = *(const float4*)(A + (size_t)(m0 + m) * K + k0 + aCol);
            As[aCol + 0][m] = va.x;
            As[aCol + 1][m] = va.y;
            As[aCol + 2][m] = va.z;
            As[aCol + 3][m] = va.w;
        }
        // ---- load B tile: Bs[k][n] ----
        if (TRANSB) {
#pragma unroll
            for (int r = 0; r < 2; ++r) {
                const int n = aRow + r * 64;
                float4 vb = make_float4(0.f, 0.f, 0.f, 0.f);
                if (n0 + n < N)
                    vb = *(const float4*)(B + (size_t)(n0 + n) * K + k0 + aCol);
                Bs[aCol + 0][n] = vb.x;
                Bs[aCol + 1][n] = vb.y;
                Bs[aCol + 2][n] = vb.z;
                Bs[aCol + 3][n] = vb.w;
            }
        } else {
#pragma unroll
            for (int r = 0; r < 2; ++r) {
                const int kk = bRowNN + r * 8;
                float4 vb;
                if (n0 + bColNN + 3 < N) {
                    vb = *(const float4*)(B + (size_t)(k0 + kk) * N + n0 + bColNN);
                } else {
                    float tmp[4];
#pragma unroll
                    for (int e = 0; e < 4; ++e) {
                        const int c = n0 + bColNN + e;
                        tmp[e] = (c < N) ? B[(size_t)(k0 + kk) * N + c] : 0.f;
                    }
                    vb = make_float4(tmp[0], tmp[1], tmp[2], tmp[3]);
                }
                *(float4*)(&Bs[kk][bColNN]) = vb;
            }
        }
        __syncthreads();

        // ---- compute: 8x8 per thread, packed f32x2 FMA ----
#pragma unroll
        for (int k = 0; k < BK; ++k) {
            const float4 a0 = *(const float4*)(&As[k][ty * 8]);
            const float4 a1 = *(const float4*)(&As[k][ty * 8 + 4]);
            const ulonglong2 bb0 = *(const ulonglong2*)(&Bs[k][tx * 8]);
            const ulonglong2 bb1 = *(const ulonglong2*)(&Bs[k][tx * 8 + 4]);
            const unsigned long long bfr[4] = {bb0.x, bb0.y, bb1.x, bb1.y};
            const float afr[8] = {a0.x, a0.y, a0.z, a0.w, a1.x, a1.y, a1.z, a1.w};
#pragma unroll
            for (int i = 0; i < 8; ++i) {
                const unsigned long long av = pack2(afr[i], afr[i]);
#pragma unroll
                for (int j = 0; j < 4; ++j) fma2(acc[i][j], av, bfr[j]);
            }
        }
        __syncthreads();
    }

    // ---- epilogue ----
    const float lsv = (mode == MODE_LS) ? expf(lsp[0]) : 1.f;

#pragma unroll
    for (int i = 0; i < 8; ++i) {
        const int row = m0 + ty * 8 + i;
#pragma unroll
        for (int j2 = 0; j2 < 4; ++j2) {
            const float2 v2 = unpack2(acc[i][j2]);
            const float vals[2] = {v2.x, v2.y};
#pragma unroll
            for (int e = 0; e < 2; ++e) {
                const int c = n0 + tx * 8 + j2 * 2 + e;
                if (c >= N) continue;
                const float x = vals[e];
                if (mode == MODE_SCALE) {
                    C[(size_t)row * N + c] = x * scale;
                } else if (mode == MODE_BNRELU) {
                    float h = x + bias[c];
                    h = (h - mean[c]) * rsqrtf(var[c] + 1e-5f) * gam[c] + bet[c];
                    C[(size_t)row * N + c] = fmaxf(h, 0.f);
                } else if (mode == MODE_QKV) {
                    const float h = x + bias[c];
                    const int which = c % 3;
                    const int d = c / 3;
                    const int ld = N / 3;
                    float* dst = (which == 0) ? qo : ((which == 1) ? ko : vo);
                    if (dst) dst[(size_t)row * ld + d] = h;
                } else if (mode == MODE_RESID) {
                    C[(size_t)row * N + c] = x + bias[c] + resid[(size_t)row * N + c];
                } else { // MODE_LS
                    C[(size_t)row * N + c] = x * lsv;
                }
            }
        }
    }
}

// ---------------------------------------------------------------------------
// Row softmax over 8192 cols, single read + single write (row in registers).
// One block (256 threads) per row; 32 elements/thread.
// ---------------------------------------------------------------------------
__global__ void softmax8192_kernel(float* __restrict__ S)
{
    float* p = S + (size_t)blockIdx.x * 8192;
    const int tid = threadIdx.x;
    const int lane = tid & 31, w = tid >> 5;

    float v[32];
    float mx = -3.4e38f;
#pragma unroll
    for (int i = 0; i < 32; ++i) {
        v[i] = p[tid + (i << 8)];
        mx = fmaxf(mx, v[i]);
    }
    __shared__ float shm[8];
#pragma unroll
    for (int o = 16; o > 0; o >>= 1) mx = fmaxf(mx, __shfl_xor_sync(0xffffffffu, mx, o));
    if (lane == 0) shm[w] = mx;
    __syncthreads();
    if (tid == 0) {
        float m = shm[0];
#pragma unroll
        for (int i = 1; i < 8; ++i) m = fmaxf(m, shm[i]);
        shm[0] = m;
    }
    __syncthreads();
    mx = shm[0];

    float s = 0.f;
#pragma unroll
    for (int i = 0; i < 32; ++i) {
        v[i] = expf(v[i] - mx);
        s += v[i];
    }
    __shared__ float shs[8];
#pragma unroll
    for (int o = 16; o > 0; o >>= 1) s += __shfl_xor_sync(0xffffffffu, s, o);
    if (lane == 0) shs[w] = s;
    __syncthreads();
    if (tid == 0) {
        float t = 0.f;
#pragma unroll
        for (int i = 0; i < 8; ++i) t += shs[i];
        shs[0] = t;
    }
    __syncthreads();
    const float inv = 1.f / shs[0];
#pragma unroll
    for (int i = 0; i < 32; ++i) p[tid + (i << 8)] = v[i] * inv;
}

// ---------------------------------------------------------------------------
// Row L2-normalize (D=1024) and write/accumulate into G.
// One block (256 threads) per row; float4 per thread.
// ---------------------------------------------------------------------------
__global__ void norm_acc_kernel(const float* __restrict__ F, float* __restrict__ G,
                                int accumulate)
{
    const float* p = F + (size_t)blockIdx.x * 1024;
    float* q = G + (size_t)blockIdx.x * 1024;
    const int tid = threadIdx.x;
    const int lane = tid & 31, w = tid >> 5;

    const float4 v = *(const float4*)(p + tid * 4);
    float ss = v.x * v.x + v.y * v.y + v.z * v.z + v.w * v.w;
#pragma unroll
    for (int o = 16; o > 0; o >>= 1) ss += __shfl_xor_sync(0xffffffffu, ss, o);
    __shared__ float sh[8];
    if (lane == 0) sh[w] = ss;
    __syncthreads();
    if (tid == 0) {
        float t = 0.f;
#pragma unroll
        for (int i = 0; i < 8; ++i) t += sh[i];
        sh[0] = t;
    }
    __syncthreads();
    const float rn = rsqrtf(sh[0]);

    float4 o;
    if (accumulate) {
        const float4 g0 = *(const float4*)(q + tid * 4);
        o = make_float4(g0.x + v.x * rn, g0.y + v.y * rn,
                        g0.z + v.z * rn, g0.w + v.w * rn);
    } else {
        o = make_float4(v.x * rn, v.y * rn, v.z * rn, v.w * rn);
    }
    *(float4*)(q + tid * 4) = o;
}

// ---------------------------------------------------------------------------
// Host side
// ---------------------------------------------------------------------------
static void launch_gemm(bool transB, const float* A, const float* B, float* C,
                        int M, int N, int K, int mode, float scale,
                        const float* bias, const float* gam, const float* bet,
                        const float* mean, const float* var,
                        const float* resid, const float* lsp,
                        float* qo, float* ko, float* vo)
{
    dim3 grid((N + BN - 1) / BN, M / BM);
    dim3 blk(GEMM_THREADS);
    if (transB)
        gemm_kernel<true><<<grid, blk>>>(A, B, C, M, N, K, mode, scale, bias,
                                         gam, bet, mean, var, resid, lsp, qo, ko, vo);
    else
        gemm_kernel<false><<<grid, blk>>>(A, B, C, M, N, K, mode, scale, bias,
                                          gam, bet, mean, var, resid, lsp, qo, ko, vo);
}

extern "C" void kernel_launch(void* const* d_in, const int* in_sizes, int n_in,
                              void* d_out, int out_size)
{
    (void)in_sizes; (void)n_in; (void)out_size;
    const float* Ft  = (const float*)d_in[0];
    const float* Fv  = (const float*)d_in[1];
    const float* Fvs = (const float*)d_in[2];
    const float* Fvt = (const float*)d_in[3];
    const float* W1  = (const float*)d_in[4];
    const float* b1  = (const float*)d_in[5];
    const float* g1  = (const float*)d_in[6];
    const float* be1 = (const float*)d_in[7];
    const float* m1  = (const float*)d_in[8];
    const float* v1  = (const float*)d_in[9];
    const float* W2  = (const float*)d_in[10];
    const float* b2  = (const float*)d_in[11];
    const float* g2  = (const float*)d_in[12];
    const float* be2 = (const float*)d_in[13];
    const float* m2  = (const float*)d_in[14];
    const float* v2  = (const float*)d_in[15];
    const float* W3  = (const float*)d_in[16];
    const float* b3  = (const float*)d_in[17];
    const float* Wp  = (const float*)d_in[18];
    const float* bp  = (const float*)d_in[19];
    const float* ls  = (const float*)d_in[20];
    float* out = (float*)d_out;

    float *H1, *H2, *Q, *Kb, *Vb, *S, *AV, *F, *G;
    cudaGetSymbolAddress((void**)&H1, g_H1);
    cudaGetSymbolAddress((void**)&H2, g_H2);
    cudaGetSymbolAddress((void**)&Q,  g_Q);
    cudaGetSymbolAddress((void**)&Kb, g_K);
    cudaGetSymbolAddress((void**)&Vb, g_V);
    cudaGetSymbolAddress((void**)&S,  g_S);
    cudaGetSymbolAddress((void**)&AV, g_AV);
    cudaGetSymbolAddress((void**)&F,  g_F);
    cudaGetSymbolAddress((void**)&G,  g_G);

    const int Bq = 4096, Nb = 8192, D = 1024, P = 128, C = 1000;

    // ---- pre_project(Fv) -> Q only ----
    launch_gemm(true, Fv, W1, H1, Bq, P, D, MODE_BNRELU, 1.f,
                b1, g1, be1, m1, v1, nullptr, nullptr, nullptr, nullptr, nullptr);
    launch_gemm(true, H1, W2, H2, Bq, P, P, MODE_BNRELU, 1.f,
                b2, g2, be2, m2, v2, nullptr, nullptr, nullptr, nullptr, nullptr);
    launch_gemm(true, H2, W3, nullptr, Bq, 3 * D, P, MODE_QKV, 1.f,
                b3, nullptr, nullptr, nullptr, nullptr, nullptr, nullptr,
                Q, nullptr, nullptr);

    // ---- per bank: pre_project -> K,V; attention; Wp + resid; normalize+acc ----
    for (int t = 0; t < 2; ++t) {
        const float* bank = t ? Fvt : Fvs;

        launch_gemm(true, bank, W1, H1, Nb, P, D, MODE_BNRELU, 1.f,
                    b1, g1, be1, m1, v1, nullptr, nullptr, nullptr, nullptr, nullptr);
        launch_gemm(true, H1, W2, H2, Nb, P, P, MODE_BNRELU, 1.f,
                    b2, g2, be2, m2, v2, nullptr, nullptr, nullptr, nullptr, nullptr);
        launch_gemm(true, H2, W3, nullptr, Nb, 3 * D, P, MODE_QKV, 1.f,
                    b3, nullptr, nullptr, nullptr, nullptr, nullptr, nullptr,
                    nullptr, Kb, Vb);

        // S = 0.1 * Q @ K^T
        launch_gemm(true, Q, Kb, S, Bq, Nb, D, MODE_SCALE, 0.1f,
                    nullptr, nullptr, nullptr, nullptr, nullptr, nullptr, nullptr,
                    nullptr, nullptr, nullptr);
        softmax8192_kernel<<<Bq, 256>>>(S);

        // AV = S @ V
        launch_gemm(false, S, Vb, AV, Bq, D, Nb, MODE_SCALE, 1.f,
                    nullptr, nullptr, nullptr, nullptr, nullptr, nullptr, nullptr,
                    nullptr, nullptr, nullptr);

        // F = Fv + AV @ Wp^T + bp
        launch_gemm(true, AV, Wp, F, Bq, D, D, MODE_RESID, 1.f,
                    bp, nullptr, nullptr, nullptr, nullptr, Fv, nullptr,
                    nullptr, nullptr, nullptr);

        // G (+)= F / ||F||
        norm_acc_kernel<<<Bq, 256>>>(F, G, t);
    }

    // ---- logits = exp(ls) * G @ Ft^T ----
    launch_gemm(true, G, Ft, out, Bq, C, D, MODE_LS, 1.f,
                nullptr, nullptr, nullptr, nullptr, nullptr, nullptr, ls,
                nullptr, nullptr, nullptr);
}

// round 6
// speedup vs baseline: 5.6745x; 5.6745x over previous
#include <cuda_runtime.h>
#include <cuda_bf16.h>
#include <math.h>
#include <stdint.h>

typedef __nv_bfloat16 bf16;

#define Dq 1024
#define Pq 128
#define Bq 4096
#define Nq 8192
#define Cq 1000

// ---------------- scratch (static device memory; no allocations) -----------
__device__ bf16  g_xb [Nq * Dq];
__device__ bf16  g_W1b[Pq * Dq];
__device__ bf16  g_W2b[Pq * Pq];
__device__ bf16  g_W3b[3 * Dq * Pq];
__device__ bf16  g_Wpb[Dq * Dq];
__device__ bf16  g_H1b[Nq * Pq];
__device__ bf16  g_H2b[Nq * Pq];
__device__ bf16  g_Qb [Bq * Dq];
__device__ bf16  g_Qd [Nq * Dq];
__device__ bf16  g_Kb [Nq * Dq];
__device__ bf16  g_Vb [Nq * Dq];
__device__ bf16  g_Vt [Dq * Nq];
__device__ bf16  g_Sb [(size_t)Bq * Nq];
__device__ bf16  g_AVt[Dq * Bq];
__device__ bf16  g_AVb[Bq * Dq];
__device__ float g_F  [Bq * Dq];
__device__ float g_G  [Bq * Dq];
__device__ bf16  g_Ap [(size_t)Bq * 3 * Dq];
__device__ bf16  g_Bp [(size_t)Cq * 3 * Dq];

// ---------------- helpers ---------------------------------------------------
__device__ __forceinline__ uint32_t s2u(const void* p) {
    uint32_t a;
    asm("{ .reg .u64 t; cvta.to.shared.u64 t, %1; cvt.u32.u64 %0, t; }"
        : "=r"(a) : "l"(p));
    return a;
}
__device__ __forceinline__ void ldmx4(uint32_t* r, uint32_t a) {
    asm volatile("ldmatrix.sync.aligned.m8n8.x4.shared.b16 {%0,%1,%2,%3}, [%4];"
                 : "=r"(r[0]), "=r"(r[1]), "=r"(r[2]), "=r"(r[3]) : "r"(a));
}
__device__ __forceinline__ void mma16816(float* c, const uint32_t* a, const uint32_t* b) {
    asm volatile("mma.sync.aligned.m16n8k16.row.col.f32.bf16.bf16.f32 "
                 "{%0,%1,%2,%3}, {%4,%5,%6,%7}, {%8,%9}, {%0,%1,%2,%3};"
                 : "+f"(c[0]), "+f"(c[1]), "+f"(c[2]), "+f"(c[3])
                 : "r"(a[0]), "r"(a[1]), "r"(a[2]), "r"(a[3]),
                   "r"(b[0]), "r"(b[1]));
}
__device__ __forceinline__ void cp16(uint32_t dst, const void* src) {
    asm volatile("cp.async.cg.shared.global [%0], [%1], 16;"
                 :: "r"(dst), "l"(src));
}
__device__ __forceinline__ void cp16z(uint32_t dst, const void* src, int sz) {
    asm volatile("cp.async.cg.shared.global [%0], [%1], 16, %2;"
                 :: "r"(dst), "l"(src), "r"(sz));
}
__device__ __forceinline__ void cp_commit() {
    asm volatile("cp.async.commit_group;" ::: "memory");
}

// ---------------- mma.sync GEMM: C(MxN) = A(MxK) @ B(NxK)^T, bf16 ----------
// BM=BN=128, BK=32, 256 threads (8 warps, 2x4), 3-stage cp.async pipeline.
// Smem rows padded: 32 bf16 data + pad -> stride 40 bf16 (80B).
#define SROW 80                        // bytes per smem row
#define ATILE_B (128 * SROW)           // 10240
#define STAGE_B (2 * ATILE_B)          // 20480 (A then B)
#define NSTAGE  3
#define SMEM_SZ (NSTAGE * STAGE_B)     // 61440

#define MODE_SMUL   0  // bf16 out = acc*scale
#define MODE_BNRELU 1  // bf16 out = relu(bn(acc+bias))
#define MODE_QKV    2  // scatter bf16 to q/k/v (ld=1024)
#define MODE_RESID  3  // f32 out = acc + bias[c] + resid[row,c]
#define MODE_LS     4  // f32 out = acc * exp(*lsp), ragged-N guarded

__device__ __forceinline__ void stage_load(const bf16* __restrict__ A,
                                           const bf16* __restrict__ Bm,
                                           int N_, int K_, int m0, int n0, int k0,
                                           uint32_t sbase, int tid)
{
#pragma unroll
    for (int j = 0; j < 2; ++j) {
        const int idx = tid * 2 + j;        // 0..511
        const int row = idx >> 2;           // 0..127
        const int ch  = idx & 3;            // 16B chunk
        // A (rows always valid: M multiple of 128)
        cp16(sbase + row * SROW + ch * 16,
             A + (size_t)(m0 + row) * K_ + k0 + ch * 8);
        // B (guard ragged N)
        const int grow = n0 + row;
        const int v = (grow < N_);
        cp16z(sbase + ATILE_B + row * SROW + ch * 16,
              Bm + (size_t)(v ? grow : 0) * K_ + k0 + ch * 8, v ? 16 : 0);
    }
}

__device__ __forceinline__ void compute_stage(uint32_t sbase, int lane,
                                              int wm, int wn,
                                              float acc[4][4][4])
{
    const uint32_t aBase = sbase + (wm * 64 + (lane & 15)) * SROW + (lane >> 4) * 16;
    const uint32_t bBase = sbase + ATILE_B +
                           (wn * 32 + ((lane >> 4) << 3) + (lane & 7)) * SROW +
                           (((lane >> 3) & 1) << 4);
#pragma unroll
    for (int kh = 0; kh < 2; ++kh) {
        uint32_t af[4][4];
#pragma unroll
        for (int tm = 0; tm < 4; ++tm)
            ldmx4(af[tm], aBase + tm * 16 * SROW + kh * 32);
        uint32_t bfr[4][2];
#pragma unroll
        for (int tp = 0; tp < 2; ++tp) {
            uint32_t r[4];
            ldmx4(r, bBase + tp * 16 * SROW + kh * 32);
            bfr[2 * tp][0] = r[0];  bfr[2 * tp][1] = r[1];
            bfr[2 * tp + 1][0] = r[2]; bfr[2 * tp + 1][1] = r[3];
        }
#pragma unroll
        for (int tm = 0; tm < 4; ++tm)
#pragma unroll
            for (int tn = 0; tn < 4; ++tn)
                mma16816(acc[tm][tn], af[tm], bfr[tn]);
    }
}

__global__ __launch_bounds__(256)
void tc_gemm(const bf16* __restrict__ A, const bf16* __restrict__ Bm,
             int M, int N, int K, int mode, float scale,
             const float* __restrict__ bias, const float* __restrict__ gam,
             const float* __restrict__ bet, const float* __restrict__ mean,
             const float* __restrict__ var, const float* __restrict__ resid,
             const float* __restrict__ lsp,
             void* __restrict__ Cout,
             bf16* __restrict__ qo, bf16* __restrict__ ko, bf16* __restrict__ vo)
{
    extern __shared__ char smem[];
    const uint32_t sb = s2u(smem);
    const int tid  = threadIdx.x;
    const int lane = tid & 31;
    const int wid  = tid >> 5;
    const int wm = wid >> 2, wn = wid & 3;
    const int m0 = blockIdx.y * 128;
    const int n0 = blockIdx.x * 128;
    const int NC = K >> 5;

    float acc[4][4][4];
#pragma unroll
    for (int a = 0; a < 4; ++a)
#pragma unroll
        for (int b = 0; b < 4; ++b)
#pragma unroll
            for (int c = 0; c < 4; ++c) acc[a][b][c] = 0.f;

    // prologue: prefetch 2 stages (NC >= 4 in all our calls)
#pragma unroll
    for (int s = 0; s < 2; ++s) {
        if (s < NC) stage_load(A, Bm, N, K, m0, n0, s * 32, sb + s * STAGE_B, tid);
        cp_commit();
    }

    for (int i = 0; i < NC; ++i) {
        asm volatile("cp.async.wait_group 1;" ::: "memory");
        __syncthreads();
        compute_stage(sb + (i % NSTAGE) * STAGE_B, lane, wm, wn, acc);
        if (i + 2 < NC)
            stage_load(A, Bm, N, K, m0, n0, (i + 2) * 32,
                       sb + ((i + 2) % NSTAGE) * STAGE_B, tid);
        cp_commit();
    }
    asm volatile("cp.async.wait_group 0;" ::: "memory");

    // ---------------- epilogue ---------------------------------------------
    const float lsv = (mode == MODE_LS) ? expf(lsp[0]) : 1.f;

#pragma unroll
    for (int tm = 0; tm < 4; ++tm) {
#pragma unroll
        for (int tn = 0; tn < 4; ++tn) {
            const int r0 = m0 + wm * 64 + tm * 16 + (lane >> 2);
            const int c0 = n0 + wn * 32 + tn * 8 + 2 * (lane & 3);
#pragma unroll
            for (int h = 0; h < 2; ++h) {
                const int row = r0 + 8 * h;
                const float f0 = acc[tm][tn][2 * h];
                const float f1 = acc[tm][tn][2 * h + 1];
                if (mode == MODE_SMUL) {
                    __nv_bfloat162 p = __floats2bfloat162_rn(f0 * scale, f1 * scale);
                    *reinterpret_cast<__nv_bfloat162*>(
                        (bf16*)Cout + (size_t)row * N + c0) = p;
                } else if (mode == MODE_BNRELU) {
                    float x0 = f0 + bias[c0];
                    x0 = (x0 - mean[c0]) * rsqrtf(var[c0] + 1e-5f) * gam[c0] + bet[c0];
                    float x1 = f1 + bias[c0 + 1];
                    x1 = (x1 - mean[c0 + 1]) * rsqrtf(var[c0 + 1] + 1e-5f) * gam[c0 + 1]
                         + bet[c0 + 1];
                    __nv_bfloat162 p = __floats2bfloat162_rn(fmaxf(x0, 0.f),
                                                             fmaxf(x1, 0.f));
                    *reinterpret_cast<__nv_bfloat162*>(
                        (bf16*)Cout + (size_t)row * N + c0) = p;
                } else if (mode == MODE_QKV) {
#pragma unroll
                    for (int e = 0; e < 2; ++e) {
                        const int c2 = c0 + e;
                        const float hv = (e ? f1 : f0) + bias[c2];
                        const int d = c2 / 3;
                        const int w = c2 - d * 3;
                        bf16* dst = (w == 0) ? qo : ((w == 1) ? ko : vo);
                        dst[(size_t)row * 1024 + d] = __float2bfloat16(hv);
                    }
                } else if (mode == MODE_RESID) {
                    float* Cf = (float*)Cout + (size_t)row * N + c0;
                    const float2 rv = *reinterpret_cast<const float2*>(
                        resid + (size_t)row * N + c0);
                    float2 o;
                    o.x = f0 + bias[c0] + rv.x;
                    o.y = f1 + bias[c0 + 1] + rv.y;
                    *reinterpret_cast<float2*>(Cf) = o;
                } else { // MODE_LS (N may be ragged; N even so pair-guard ok)
                    if (c0 < N) {
                        float* Cf = (float*)Cout + (size_t)row * N + c0;
                        Cf[0] = f0 * lsv;
                        Cf[1] = f1 * lsv;
                    }
                }
            }
        }
    }
}

// ---------------- small kernels --------------------------------------------
__global__ void f2b_kernel(const float* __restrict__ in, bf16* __restrict__ out, int n)
{
    const int i = (blockIdx.x * blockDim.x + threadIdx.x) * 4;
    if (i < n) {
        const float4 v = *reinterpret_cast<const float4*>(in + i);
        __nv_bfloat162 a = __floats2bfloat162_rn(v.x, v.y);
        __nv_bfloat162 b = __floats2bfloat162_rn(v.z, v.w);
        uint2 pk;
        pk.x = *reinterpret_cast<uint32_t*>(&a);
        pk.y = *reinterpret_cast<uint32_t*>(&b);
        *reinterpret_cast<uint2*>(out + i) = pk;
    }
}

// transpose bf16 (R x C) -> (C x R); R,C multiples of 32
__global__ void transpose_bf16(const bf16* __restrict__ in, bf16* __restrict__ out,
                               int R, int C)
{
    __shared__ bf16 t[32][33];
    const int c0 = blockIdx.x * 32, r0 = blockIdx.y * 32;
    const int tx = threadIdx.x, ty = threadIdx.y;
#pragma unroll
    for (int i = 0; i < 4; ++i)
        t[ty + i * 8][tx] = in[(size_t)(r0 + ty + i * 8) * C + c0 + tx];
    __syncthreads();
#pragma unroll
    for (int i = 0; i < 4; ++i)
        out[(size_t)(c0 + ty + i * 8) * R + r0 + tx] = t[tx][ty + i * 8];
}

// in-place row softmax over 8192 bf16 cols
__global__ void softmax_bf16(bf16* __restrict__ S)
{
    bf16* p = S + (size_t)blockIdx.x * 8192;
    const int tid = threadIdx.x;
    const int lane = tid & 31, w = tid >> 5;

    float v[32];
    float mx = -3.4e38f;
#pragma unroll
    for (int i = 0; i < 32; ++i) {
        v[i] = __bfloat162float(p[tid + (i << 8)]);
        mx = fmaxf(mx, v[i]);
    }
    __shared__ float shm[8], shs[8];
#pragma unroll
    for (int o = 16; o > 0; o >>= 1) mx = fmaxf(mx, __shfl_xor_sync(0xffffffffu, mx, o));
    if (lane == 0) shm[w] = mx;
    __syncthreads();
    if (tid == 0) {
        float m = shm[0];
#pragma unroll
        for (int i = 1; i < 8; ++i) m = fmaxf(m, shm[i]);
        shm[0] = m;
    }
    __syncthreads();
    mx = shm[0];

    float s = 0.f;
#pragma unroll
    for (int i = 0; i < 32; ++i) { v[i] = expf(v[i] - mx); s += v[i]; }
#pragma unroll
    for (int o = 16; o > 0; o >>= 1) s += __shfl_xor_sync(0xffffffffu, s, o);
    if (lane == 0) shs[w] = s;
    __syncthreads();
    if (tid == 0) {
        float t = 0.f;
#pragma unroll
        for (int i = 0; i < 8; ++i) t += shs[i];
        shs[0] = t;
    }
    __syncthreads();
    const float inv = 1.f / shs[0];
#pragma unroll
    for (int i = 0; i < 32; ++i) p[tid + (i << 8)] = __float2bfloat16(v[i] * inv);
}

// row L2-normalize (D=1024) F -> accumulate into G
__global__ void norm_acc_kernel(const float* __restrict__ F, float* __restrict__ G,
                                int accumulate)
{
    const float* p = F + (size_t)blockIdx.x * 1024;
    float* q = G + (size_t)blockIdx.x * 1024;
    const int tid = threadIdx.x;
    const int lane = tid & 31, w = tid >> 5;

    const float4 v = *reinterpret_cast<const float4*>(p + tid * 4);
    float ss = v.x * v.x + v.y * v.y + v.z * v.z + v.w * v.w;
#pragma unroll
    for (int o = 16; o > 0; o >>= 1) ss += __shfl_xor_sync(0xffffffffu, ss, o);
    __shared__ float sh[8];
    if (lane == 0) sh[w] = ss;
    __syncthreads();
    if (tid == 0) {
        float t = 0.f;
#pragma unroll
        for (int i = 0; i < 8; ++i) t += sh[i];
        sh[0] = t;
    }
    __syncthreads();
    const float rn = rsqrtf(sh[0]);

    float4 o;
    if (accumulate) {
        const float4 g0 = *reinterpret_cast<const float4*>(q + tid * 4);
        o = make_float4(g0.x + v.x * rn, g0.y + v.y * rn,
                        g0.z + v.z * rn, g0.w + v.w * rn);
    } else {
        o = make_float4(v.x * rn, v.y * rn, v.z * rn, v.w * rn);
    }
    *reinterpret_cast<float4*>(q + tid * 4) = o;
}

// A' = [Gh | Gh | Gl]  (Bq x 3D)
__global__ void build_Ap_kernel(const float* __restrict__ G, bf16* __restrict__ Ap)
{
    const int idx = blockIdx.x * blockDim.x + threadIdx.x;
    if (idx >= Bq * Dq) return;
    const int r = idx >> 10, c = idx & 1023;
    const float v = G[idx];
    const bf16 h = __float2bfloat16(v);
    const bf16 l = __float2bfloat16(v - __bfloat162float(h));
    bf16* row = Ap + (size_t)r * 3072;
    row[c] = h; row[1024 + c] = h; row[2048 + c] = l;
}

// B' = [Fh | Fl | Fh]  (Cq x 3D)
__global__ void build_Bp_kernel(const float* __restrict__ Ft, bf16* __restrict__ Bp)
{
    const int idx = blockIdx.x * blockDim.x + threadIdx.x;
    if (idx >= Cq * Dq) return;
    const int r = idx >> 10, c = idx & 1023;
    const float v = Ft[idx];
    const bf16 h = __float2bfloat16(v);
    const bf16 l = __float2bfloat16(v - __bfloat162float(h));
    bf16* row = Bp + (size_t)r * 3072;
    row[c] = h; row[1024 + c] = l; row[2048 + c] = h;
}

// ---------------- host side ------------------------------------------------
static void tc(const bf16* A, const bf16* B, int M, int N, int K, int mode,
               float scale, const float* bias, const float* gam, const float* bet,
               const float* mean, const float* var, const float* resid,
               const float* lsp, void* C, bf16* qo, bf16* ko, bf16* vo)
{
    dim3 grid((N + 127) / 128, M / 128);
    tc_gemm<<<grid, 256, SMEM_SZ>>>(A, B, M, N, K, mode, scale, bias, gam, bet,
                                    mean, var, resid, lsp, C, qo, ko, vo);
}

static void f2b(const float* in, bf16* out, int n)
{
    f2b_kernel<<<(n / 4 + 255) / 256, 256>>>(in, out, n);
}

extern "C" void kernel_launch(void* const* d_in, const int* in_sizes, int n_in,
                              void* d_out, int out_size)
{
    (void)in_sizes; (void)n_in; (void)out_size;
    const float* Ft  = (const float*)d_in[0];
    const float* Fv  = (const float*)d_in[1];
    const float* Fvs = (const float*)d_in[2];
    const float* Fvt = (const float*)d_in[3];
    const float* W1  = (const float*)d_in[4];
    const float* b1  = (const float*)d_in[5];
    const float* g1  = (const float*)d_in[6];
    const float* be1 = (const float*)d_in[7];
    const float* m1  = (const float*)d_in[8];
    const float* v1  = (const float*)d_in[9];
    const float* W2  = (const float*)d_in[10];
    const float* b2  = (const float*)d_in[11];
    const float* g2  = (const float*)d_in[12];
    const float* be2 = (const float*)d_in[13];
    const float* m2  = (const float*)d_in[14];
    const float* v2  = (const float*)d_in[15];
    const float* W3  = (const float*)d_in[16];
    const float* b3  = (const float*)d_in[17];
    const float* Wp  = (const float*)d_in[18];
    const float* bp  = (const float*)d_in[19];
    const float* ls  = (const float*)d_in[20];
    float* out = (float*)d_out;

    static int inited = 0;
    cudaFuncSetAttribute(tc_gemm, cudaFuncAttributeMaxDynamicSharedMemorySize, SMEM_SZ);
    (void)inited;

    bf16 *xb, *W1b, *W2b, *W3b, *Wpb, *H1b, *H2b, *Qb, *Qd, *Kb, *Vb, *Vt, *Sb, *AVt, *AVb, *Ap, *Bp;
    float *F, *G;
    cudaGetSymbolAddress((void**)&xb,  g_xb);
    cudaGetSymbolAddress((void**)&W1b, g_W1b);
    cudaGetSymbolAddress((void**)&W2b, g_W2b);
    cudaGetSymbolAddress((void**)&W3b, g_W3b);
    cudaGetSymbolAddress((void**)&Wpb, g_Wpb);
    cudaGetSymbolAddress((void**)&H1b, g_H1b);
    cudaGetSymbolAddress((void**)&H2b, g_H2b);
    cudaGetSymbolAddress((void**)&Qb,  g_Qb);
    cudaGetSymbolAddress((void**)&Qd,  g_Qd);
    cudaGetSymbolAddress((void**)&Kb,  g_Kb);
    cudaGetSymbolAddress((void**)&Vb,  g_Vb);
    cudaGetSymbolAddress((void**)&Vt,  g_Vt);
    cudaGetSymbolAddress((void**)&Sb,  g_Sb);
    cudaGetSymbolAddress((void**)&AVt, g_AVt);
    cudaGetSymbolAddress((void**)&AVb, g_AVb);
    cudaGetSymbolAddress((void**)&F,   g_F);
    cudaGetSymbolAddress((void**)&G,   g_G);
    cudaGetSymbolAddress((void**)&Ap,  g_Ap);
    cudaGetSymbolAddress((void**)&Bp,  g_Bp);

    // weight conversions
    f2b(W1, W1b, Pq * Dq);
    f2b(W2, W2b, Pq * Pq);
    f2b(W3, W3b, 3 * Dq * Pq);
    f2b(Wp, Wpb, Dq * Dq);

    // ---- pre_project(Fv) -> Q ----
    f2b(Fv, xb, Bq * Dq);
    tc(xb,  W1b, Bq, Pq, Dq, MODE_BNRELU, 1.f, b1, g1, be1, m1, v1,
       nullptr, nullptr, H1b, nullptr, nullptr, nullptr);
    tc(H1b, W2b, Bq, Pq, Pq, MODE_BNRELU, 1.f, b2, g2, be2, m2, v2,
       nullptr, nullptr, H2b, nullptr, nullptr, nullptr);
    tc(H2b, W3b, Bq, 3 * Dq, Pq, MODE_QKV, 1.f, b3, nullptr, nullptr, nullptr,
       nullptr, nullptr, nullptr, nullptr, Qb, Kb, Vb);

    // ---- per bank ----
    for (int t = 0; t < 2; ++t) {
        const float* bank = t ? Fvt : Fvs;
        f2b(bank, xb, Nq * Dq);
        tc(xb,  W1b, Nq, Pq, Dq, MODE_BNRELU, 1.f, b1, g1, be1, m1, v1,
           nullptr, nullptr, H1b, nullptr, nullptr, nullptr);
        tc(H1b, W2b, Nq, Pq, Pq, MODE_BNRELU, 1.f, b2, g2, be2, m2, v2,
           nullptr, nullptr, H2b, nullptr, nullptr, nullptr);
        tc(H2b, W3b, Nq, 3 * Dq, Pq, MODE_QKV, 1.f, b3, nullptr, nullptr, nullptr,
           nullptr, nullptr, nullptr, nullptr, Qd, Kb, Vb);

        // V^T for the A@V GEMM
        transpose_bf16<<<dim3(Dq / 32, Nq / 32), dim3(32, 8)>>>(Vb, Vt, Nq, Dq);

        // S = 0.1 * Q @ K^T   (bf16 out)
        tc(Qb, Kb, Bq, Nq, Dq, MODE_SMUL, 0.1f, nullptr, nullptr, nullptr,
           nullptr, nullptr, nullptr, nullptr, Sb, nullptr, nullptr, nullptr);
        softmax_bf16<<<Bq, 256>>>(Sb);

        // AV^T(d,b) = Vt @ S^T
        tc(Vt, Sb, Dq, Bq, Nq, MODE_SMUL, 1.f, nullptr, nullptr, nullptr,
           nullptr, nullptr, nullptr, nullptr, AVt, nullptr, nullptr, nullptr);
        transpose_bf16<<<dim3(Bq / 32, Dq / 32), dim3(32, 8)>>>(AVt, AVb, Dq, Bq);

        // F = Fv + AV @ Wp^T + bp   (fp32)
        tc(AVb, Wpb, Bq, Dq, Dq, MODE_RESID, 1.f, bp, nullptr, nullptr,
           nullptr, nullptr, Fv, nullptr, F, nullptr, nullptr, nullptr);

        norm_acc_kernel<<<Bq, 256>>>(F, G, t);
    }

    // ---- logits = exp(ls) * G @ Ft^T via bf16 split (3-term) ----
    build_Ap_kernel<<<(Bq * Dq + 255) / 256, 256>>>(G, Ap);
    build_Bp_kernel<<<(Cq * Dq + 255) / 256, 256>>>(Ft, Bp);
    tc(Ap, Bp, Bq, Cq, 3 * Dq, MODE_LS, 1.f, nullptr, nullptr, nullptr,
       nullptr, nullptr, nullptr, ls, out, nullptr, nullptr, nullptr);
}

// round 7
// speedup vs baseline: 6.8862x; 1.2135x over previous
#include <cuda_runtime.h>
#include <cuda_bf16.h>
#include <math.h>
#include <stdint.h>

typedef __nv_bfloat16 bf16;

#define Dq 1024
#define Pq 128
#define Bq 4096
#define Nq 8192
#define Cq 1000

// ---------------- scratch (static device memory; no allocations) -----------
__device__ bf16  g_xb [Nq * Dq];
__device__ bf16  g_W1b[Pq * Dq];
__device__ bf16  g_W2b[Pq * Pq];
__device__ bf16  g_W3b[3 * Dq * Pq];
__device__ bf16  g_Wpb[Dq * Dq];
__device__ bf16  g_H1b[Nq * Pq];
__device__ bf16  g_H2b[Nq * Pq];
__device__ bf16  g_Qb [Bq * Dq];
__device__ bf16  g_Kb [Nq * Dq];
__device__ bf16  g_Vb [Nq * Dq];
__device__ bf16  g_Vt [Dq * Nq];
__device__ bf16  g_Sb [(size_t)Bq * Nq];
__device__ bf16  g_AVt[Dq * Bq];
__device__ bf16  g_AVb[Bq * Dq];
__device__ float g_F  [Bq * Dq];
__device__ float g_G  [Bq * Dq];
__device__ bf16  g_Ap [(size_t)Bq * 3 * Dq];
__device__ bf16  g_Bp [(size_t)Cq * 3 * Dq];

// ---------------- helpers ---------------------------------------------------
__device__ __forceinline__ uint32_t s2u(const void* p) {
    uint32_t a;
    asm("{ .reg .u64 t; cvta.to.shared.u64 t, %1; cvt.u32.u64 %0, t; }"
        : "=r"(a) : "l"(p));
    return a;
}
__device__ __forceinline__ void ldmx4(uint32_t* r, uint32_t a) {
    asm volatile("ldmatrix.sync.aligned.m8n8.x4.shared.b16 {%0,%1,%2,%3}, [%4];"
                 : "=r"(r[0]), "=r"(r[1]), "=r"(r[2]), "=r"(r[3]) : "r"(a));
}
__device__ __forceinline__ void mma16816(float* c, const uint32_t* a, const uint32_t* b) {
    asm volatile("mma.sync.aligned.m16n8k16.row.col.f32.bf16.bf16.f32 "
                 "{%0,%1,%2,%3}, {%4,%5,%6,%7}, {%8,%9}, {%0,%1,%2,%3};"
                 : "+f"(c[0]), "+f"(c[1]), "+f"(c[2]), "+f"(c[3])
                 : "r"(a[0]), "r"(a[1]), "r"(a[2]), "r"(a[3]),
                   "r"(b[0]), "r"(b[1]));
}
__device__ __forceinline__ void cp16(uint32_t dst, const void* src) {
    asm volatile("cp.async.cg.shared.global [%0], [%1], 16;"
                 :: "r"(dst), "l"(src));
}
__device__ __forceinline__ void cp16z(uint32_t dst, const void* src, int sz) {
    asm volatile("cp.async.cg.shared.global [%0], [%1], 16, %2;"
                 :: "r"(dst), "l"(src), "r"(sz));
}
__device__ __forceinline__ void cp_commit() {
    asm volatile("cp.async.commit_group;" ::: "memory");
}

// ---------------- mma.sync GEMM: C(MxN) = A(MxK) @ B(NxK)^T, bf16 ----------
// BM=128, BN template (128 or 256), BK=32, 2*BN threads, 3-stage cp.async.
// Smem rows padded: 32 bf16 data -> stride 40 bf16 (80B).
#define SROW 80
#define ATILE_B (128 * SROW)           // 10240
#define NSTAGE  3

#define MODE_SMUL   0  // bf16 out = acc*scale
#define MODE_BNRELU 1  // bf16 out = relu(bn(acc+bias))
#define MODE_QKV    2  // scatter bf16 to q/k/v (ld=1024), null dst skipped
#define MODE_RESID  3  // f32 out = acc + bias[c] + resid[row,c]
#define MODE_LS     4  // f32 out = acc * exp(*lsp), ragged-N guarded

template <int BN>
__device__ __forceinline__ void stage_load(const bf16* __restrict__ A,
                                           const bf16* __restrict__ Bm,
                                           int N_, int K_, int m0, int n0, int k0,
                                           uint32_t sbase, int tid)
{
    const int T = 2 * BN;
    // A: 512 16B chunks (128 rows x 4)
#pragma unroll
    for (int i = tid; i < 512; i += T) {
        const int row = i >> 2, ch = i & 3;
        cp16(sbase + row * SROW + ch * 16,
             A + (size_t)(m0 + row) * K_ + k0 + ch * 8);
    }
    // B: 4*BN chunks (BN rows x 4), ragged-N guarded
#pragma unroll
    for (int i = tid; i < 4 * BN; i += T) {
        const int row = i >> 2, ch = i & 3;
        const int grow = n0 + row;
        const int v = (grow < N_);
        cp16z(sbase + ATILE_B + row * SROW + ch * 16,
              Bm + (size_t)(v ? grow : 0) * K_ + k0 + ch * 8, v ? 16 : 0);
    }
}

__device__ __forceinline__ void compute_stage(uint32_t sbase, int lane,
                                              int wm, int wn,
                                              float acc[4][4][4])
{
    const uint32_t aBase = sbase + (wm * 64 + (lane & 15)) * SROW + (lane >> 4) * 16;
    const uint32_t bBase = sbase + ATILE_B +
                           (wn * 32 + ((lane >> 4) << 3) + (lane & 7)) * SROW +
                           (((lane >> 3) & 1) << 4);
#pragma unroll
    for (int kh = 0; kh < 2; ++kh) {
        uint32_t af[4][4];
#pragma unroll
        for (int tm = 0; tm < 4; ++tm)
            ldmx4(af[tm], aBase + tm * 16 * SROW + kh * 32);
        uint32_t bfr[4][2];
#pragma unroll
        for (int tp = 0; tp < 2; ++tp) {
            uint32_t r[4];
            ldmx4(r, bBase + tp * 16 * SROW + kh * 32);
            bfr[2 * tp][0] = r[0];  bfr[2 * tp][1] = r[1];
            bfr[2 * tp + 1][0] = r[2]; bfr[2 * tp + 1][1] = r[3];
        }
#pragma unroll
        for (int tm = 0; tm < 4; ++tm)
#pragma unroll
            for (int tn = 0; tn < 4; ++tn)
                mma16816(acc[tm][tn], af[tm], bfr[tn]);
    }
}

template <int BN>
__global__ __launch_bounds__(2 * BN)
void tc_gemm(const bf16* __restrict__ A, const bf16* __restrict__ Bm,
             int M, int N, int K, int mode, float scale,
             const float* __restrict__ bias, const float* __restrict__ gam,
             const float* __restrict__ bet, const float* __restrict__ mean,
             const float* __restrict__ var, const float* __restrict__ resid,
             const float* __restrict__ lsp,
             void* __restrict__ Cout,
             bf16* __restrict__ qo, bf16* __restrict__ ko, bf16* __restrict__ vo)
{
    constexpr int NW = BN / 32;              // warp cols
    constexpr int STAGE = ATILE_B + BN * SROW;
    extern __shared__ char smem[];
    const uint32_t sb = s2u(smem);
    const int tid  = threadIdx.x;
    const int lane = tid & 31;
    const int wid  = tid >> 5;
    const int wm = wid / NW, wn = wid % NW;
    const int m0 = blockIdx.y * 128;
    const int n0 = blockIdx.x * BN;
    const int NC = K >> 5;

    float acc[4][4][4];
#pragma unroll
    for (int a = 0; a < 4; ++a)
#pragma unroll
        for (int b = 0; b < 4; ++b)
#pragma unroll
            for (int c = 0; c < 4; ++c) acc[a][b][c] = 0.f;

    // prologue: prefetch 2 stages (NC >= 4 in all our calls)
#pragma unroll
    for (int s = 0; s < 2; ++s) {
        stage_load<BN>(A, Bm, N, K, m0, n0, s * 32, sb + s * STAGE, tid);
        cp_commit();
    }

    for (int i = 0; i < NC; ++i) {
        asm volatile("cp.async.wait_group 1;" ::: "memory");
        __syncthreads();
        compute_stage(sb + (i % NSTAGE) * STAGE, lane, wm, wn, acc);
        if (i + 2 < NC)
            stage_load<BN>(A, Bm, N, K, m0, n0, (i + 2) * 32,
                           sb + ((i + 2) % NSTAGE) * STAGE, tid);
        cp_commit();
    }
    asm volatile("cp.async.wait_group 0;" ::: "memory");

    // ---------------- epilogue ---------------------------------------------
    const float lsv = (mode == MODE_LS) ? __expf(lsp[0]) : 1.f;

#pragma unroll
    for (int tm = 0; tm < 4; ++tm) {
#pragma unroll
        for (int tn = 0; tn < 4; ++tn) {
            const int r0 = m0 + wm * 64 + tm * 16 + (lane >> 2);
            const int c0 = n0 + wn * 32 + tn * 8 + 2 * (lane & 3);
#pragma unroll
            for (int h = 0; h < 2; ++h) {
                const int row = r0 + 8 * h;
                const float f0 = acc[tm][tn][2 * h];
                const float f1 = acc[tm][tn][2 * h + 1];
                if (mode == MODE_SMUL) {
                    __nv_bfloat162 p = __floats2bfloat162_rn(f0 * scale, f1 * scale);
                    *reinterpret_cast<__nv_bfloat162*>(
                        (bf16*)Cout + (size_t)row * N + c0) = p;
                } else if (mode == MODE_BNRELU) {
                    float x0 = f0 + bias[c0];
                    x0 = (x0 - mean[c0]) * rsqrtf(var[c0] + 1e-5f) * gam[c0] + bet[c0];
                    float x1 = f1 + bias[c0 + 1];
                    x1 = (x1 - mean[c0 + 1]) * rsqrtf(var[c0 + 1] + 1e-5f) * gam[c0 + 1]
                         + bet[c0 + 1];
                    __nv_bfloat162 p = __floats2bfloat162_rn(fmaxf(x0, 0.f),
                                                             fmaxf(x1, 0.f));
                    *reinterpret_cast<__nv_bfloat162*>(
                        (bf16*)Cout + (size_t)row * N + c0) = p;
                } else if (mode == MODE_QKV) {
#pragma unroll
                    for (int e = 0; e < 2; ++e) {
                        const int c2 = c0 + e;
                        const float hv = (e ? f1 : f0) + bias[c2];
                        const int d = c2 / 3;
                        const int w = c2 - d * 3;
                        bf16* dst = (w == 0) ? qo : ((w == 1) ? ko : vo);
                        if (dst) dst[(size_t)row * 1024 + d] = __float2bfloat16(hv);
                    }
                } else if (mode == MODE_RESID) {
                    float* Cf = (float*)Cout + (size_t)row * N + c0;
                    const float2 rv = *reinterpret_cast<const float2*>(
                        resid + (size_t)row * N + c0);
                    float2 o;
                    o.x = f0 + bias[c0] + rv.x;
                    o.y = f1 + bias[c0 + 1] + rv.y;
                    *reinterpret_cast<float2*>(Cf) = o;
                } else { // MODE_LS (N ragged; N even so pair-guard ok)
                    if (c0 < N) {
                        float* Cf = (float*)Cout + (size_t)row * N + c0;
                        Cf[0] = f0 * lsv;
                        Cf[1] = f1 * lsv;
                    }
                }
            }
        }
    }
}

#define SMEM128 (NSTAGE * (ATILE_B + 128 * SROW))   // 61440
#define SMEM256 (NSTAGE * (ATILE_B + 256 * SROW))   // 92160

// ---------------- small kernels --------------------------------------------
__global__ void f2b_kernel(const float* __restrict__ in, bf16* __restrict__ out, int n)
{
    const int i = (blockIdx.x * blockDim.x + threadIdx.x) * 4;
    if (i < n) {
        const float4 v = *reinterpret_cast<const float4*>(in + i);
        __nv_bfloat162 a = __floats2bfloat162_rn(v.x, v.y);
        __nv_bfloat162 b = __floats2bfloat162_rn(v.z, v.w);
        uint2 pk;
        pk.x = *reinterpret_cast<uint32_t*>(&a);
        pk.y = *reinterpret_cast<uint32_t*>(&b);
        *reinterpret_cast<uint2*>(out + i) = pk;
    }
}

// transpose bf16 (R x C) -> (C x R); R,C multiples of 32
__global__ void transpose_bf16(const bf16* __restrict__ in, bf16* __restrict__ out,
                               int R, int C)
{
    __shared__ bf16 t[32][33];
    const int c0 = blockIdx.x * 32, r0 = blockIdx.y * 32;
    const int tx = threadIdx.x, ty = threadIdx.y;
#pragma unroll
    for (int i = 0; i < 4; ++i)
        t[ty + i * 8][tx] = in[(size_t)(r0 + ty + i * 8) * C + c0 + tx];
    __syncthreads();
#pragma unroll
    for (int i = 0; i < 4; ++i)
        out[(size_t)(c0 + ty + i * 8) * R + r0 + tx] = t[tx][ty + i * 8];
}

// in-place row softmax over 8192 bf16 cols
__global__ void softmax_bf16(bf16* __restrict__ S)
{
    bf16* p = S + (size_t)blockIdx.x * 8192;
    const int tid = threadIdx.x;
    const int lane = tid & 31, w = tid >> 5;

    float v[32];
    float mx = -3.4e38f;
#pragma unroll
    for (int i = 0; i < 16; ++i) {
        const __nv_bfloat162 h2 = *reinterpret_cast<const __nv_bfloat162*>(
            p + tid * 2 + (i << 9));
        const float2 f2 = __bfloat1622float2(h2);
        v[2 * i] = f2.x; v[2 * i + 1] = f2.y;
        mx = fmaxf(mx, fmaxf(f2.x, f2.y));
    }
    __shared__ float shm[8], shs[8];
#pragma unroll
    for (int o = 16; o > 0; o >>= 1) mx = fmaxf(mx, __shfl_xor_sync(0xffffffffu, mx, o));
    if (lane == 0) shm[w] = mx;
    __syncthreads();
    if (tid == 0) {
        float m = shm[0];
#pragma unroll
        for (int i = 1; i < 8; ++i) m = fmaxf(m, shm[i]);
        shm[0] = m;
    }
    __syncthreads();
    mx = shm[0];

    float s = 0.f;
#pragma unroll
    for (int i = 0; i < 32; ++i) { v[i] = __expf(v[i] - mx); s += v[i]; }
#pragma unroll
    for (int o = 16; o > 0; o >>= 1) s += __shfl_xor_sync(0xffffffffu, s, o);
    if (lane == 0) shs[w] = s;
    __syncthreads();
    if (tid == 0) {
        float t = 0.f;
#pragma unroll
        for (int i = 0; i < 8; ++i) t += shs[i];
        shs[0] = t;
    }
    __syncthreads();
    const float inv = 1.f / shs[0];
#pragma unroll
    for (int i = 0; i < 16; ++i) {
        const __nv_bfloat162 h2 = __floats2bfloat162_rn(v[2 * i] * inv,
                                                        v[2 * i + 1] * inv);
        *reinterpret_cast<__nv_bfloat162*>(p + tid * 2 + (i << 9)) = h2;
    }
}

// row L2-normalize (D=1024) F -> accumulate into G
__global__ void norm_acc_kernel(const float* __restrict__ F, float* __restrict__ G,
                                int accumulate)
{
    const float* p = F + (size_t)blockIdx.x * 1024;
    float* q = G + (size_t)blockIdx.x * 1024;
    const int tid = threadIdx.x;
    const int lane = tid & 31, w = tid >> 5;

    const float4 v = *reinterpret_cast<const float4*>(p + tid * 4);
    float ss = v.x * v.x + v.y * v.y + v.z * v.z + v.w * v.w;
#pragma unroll
    for (int o = 16; o > 0; o >>= 1) ss += __shfl_xor_sync(0xffffffffu, ss, o);
    __shared__ float sh[8];
    if (lane == 0) sh[w] = ss;
    __syncthreads();
    if (tid == 0) {
        float t = 0.f;
#pragma unroll
        for (int i = 0; i < 8; ++i) t += sh[i];
        sh[0] = t;
    }
    __syncthreads();
    const float rn = rsqrtf(sh[0]);

    float4 o;
    if (accumulate) {
        const float4 g0 = *reinterpret_cast<const float4*>(q + tid * 4);
        o = make_float4(g0.x + v.x * rn, g0.y + v.y * rn,
                        g0.z + v.z * rn, g0.w + v.w * rn);
    } else {
        o = make_float4(v.x * rn, v.y * rn, v.z * rn, v.w * rn);
    }
    *reinterpret_cast<float4*>(q + tid * 4) = o;
}

// A' = [Gh | Gh | Gl]  (Bq x 3D)
__global__ void build_Ap_kernel(const float* __restrict__ G, bf16* __restrict__ Ap)
{
    const int idx = blockIdx.x * blockDim.x + threadIdx.x;
    if (idx >= Bq * Dq) return;
    const int r = idx >> 10, c = idx & 1023;
    const float v = G[idx];
    const bf16 h = __float2bfloat16(v);
    const bf16 l = __float2bfloat16(v - __bfloat162float(h));
    bf16* row = Ap + (size_t)r * 3072;
    row[c] = h; row[1024 + c] = h; row[2048 + c] = l;
}

// B' = [Fh | Fl | Fh]  (Cq x 3D)
__global__ void build_Bp_kernel(const float* __restrict__ Ft, bf16* __restrict__ Bp)
{
    const int idx = blockIdx.x * blockDim.x + threadIdx.x;
    if (idx >= Cq * Dq) return;
    const int r = idx >> 10, c = idx & 1023;
    const float v = Ft[idx];
    const bf16 h = __float2bfloat16(v);
    const bf16 l = __float2bfloat16(v - __bfloat162float(h));
    bf16* row = Bp + (size_t)r * 3072;
    row[c] = h; row[1024 + c] = l; row[2048 + c] = h;
}

// ---------------- host side ------------------------------------------------
static void tc(const bf16* A, const bf16* B, int M, int N, int K, int mode,
               float scale, const float* bias, const float* gam, const float* bet,
               const float* mean, const float* var, const float* resid,
               const float* lsp, void* C, bf16* qo, bf16* ko, bf16* vo)
{
    if ((N & 255) == 0 && (size_t)(M / 128) * (N / 256) >= 100) {
        dim3 grid(N / 256, M / 128);
        tc_gemm<256><<<grid, 512, SMEM256>>>(A, B, M, N, K, mode, scale, bias,
                                             gam, bet, mean, var, resid, lsp,
                                             C, qo, ko, vo);
    } else {
        dim3 grid((N + 127) / 128, M / 128);
        tc_gemm<128><<<grid, 256, SMEM128>>>(A, B, M, N, K, mode, scale, bias,
                                             gam, bet, mean, var, resid, lsp,
                                             C, qo, ko, vo);
    }
}

static void f2b(const float* in, bf16* out, int n)
{
    f2b_kernel<<<(n / 4 + 255) / 256, 256>>>(in, out, n);
}

extern "C" void kernel_launch(void* const* d_in, const int* in_sizes, int n_in,
                              void* d_out, int out_size)
{
    (void)in_sizes; (void)n_in; (void)out_size;
    const float* Ft  = (const float*)d_in[0];
    const float* Fv  = (const float*)d_in[1];
    const float* Fvs = (const float*)d_in[2];
    const float* Fvt = (const float*)d_in[3];
    const float* W1  = (const float*)d_in[4];
    const float* b1  = (const float*)d_in[5];
    const float* g1  = (const float*)d_in[6];
    const float* be1 = (const float*)d_in[7];
    const float* m1  = (const float*)d_in[8];
    const float* v1  = (const float*)d_in[9];
    const float* W2  = (const float*)d_in[10];
    const float* b2  = (const float*)d_in[11];
    const float* g2  = (const float*)d_in[12];
    const float* be2 = (const float*)d_in[13];
    const float* m2  = (const float*)d_in[14];
    const float* v2  = (const float*)d_in[15];
    const float* W3  = (const float*)d_in[16];
    const float* b3  = (const float*)d_in[17];
    const float* Wp  = (const float*)d_in[18];
    const float* bp  = (const float*)d_in[19];
    const float* ls  = (const float*)d_in[20];
    float* out = (float*)d_out;

    cudaFuncSetAttribute(tc_gemm<128>, cudaFuncAttributeMaxDynamicSharedMemorySize, SMEM128);
    cudaFuncSetAttribute(tc_gemm<256>, cudaFuncAttributeMaxDynamicSharedMemorySize, SMEM256);

    bf16 *xb, *W1b, *W2b, *W3b, *Wpb, *H1b, *H2b, *Qb, *Kb, *Vb, *Vt, *Sb, *AVt, *AVb, *Ap, *Bp;
    float *F, *G;
    cudaGetSymbolAddress((void**)&xb,  g_xb);
    cudaGetSymbolAddress((void**)&W1b, g_W1b);
    cudaGetSymbolAddress((void**)&W2b, g_W2b);
    cudaGetSymbolAddress((void**)&W3b, g_W3b);
    cudaGetSymbolAddress((void**)&Wpb, g_Wpb);
    cudaGetSymbolAddress((void**)&H1b, g_H1b);
    cudaGetSymbolAddress((void**)&H2b, g_H2b);
    cudaGetSymbolAddress((void**)&Qb,  g_Qb);
    cudaGetSymbolAddress((void**)&Kb,  g_Kb);
    cudaGetSymbolAddress((void**)&Vb,  g_Vb);
    cudaGetSymbolAddress((void**)&Vt,  g_Vt);
    cudaGetSymbolAddress((void**)&Sb,  g_Sb);
    cudaGetSymbolAddress((void**)&AVt, g_AVt);
    cudaGetSymbolAddress((void**)&AVb, g_AVb);
    cudaGetSymbolAddress((void**)&F,   g_F);
    cudaGetSymbolAddress((void**)&G,   g_G);
    cudaGetSymbolAddress((void**)&Ap,  g_Ap);
    cudaGetSymbolAddress((void**)&Bp,  g_Bp);

    // weight conversions
    f2b(W1, W1b, Pq * Dq);
    f2b(W2, W2b, Pq * Pq);
    f2b(W3, W3b, 3 * Dq * Pq);
    f2b(Wp, Wpb, Dq * Dq);

    // ---- pre_project(Fv) -> Q ----
    f2b(Fv, xb, Bq * Dq);
    tc(xb,  W1b, Bq, Pq, Dq, MODE_BNRELU, 1.f, b1, g1, be1, m1, v1,
       nullptr, nullptr, H1b, nullptr, nullptr, nullptr);
    tc(H1b, W2b, Bq, Pq, Pq, MODE_BNRELU, 1.f, b2, g2, be2, m2, v2,
       nullptr, nullptr, H2b, nullptr, nullptr, nullptr);
    tc(H2b, W3b, Bq, 3 * Dq, Pq, MODE_QKV, 1.f, b3, nullptr, nullptr, nullptr,
       nullptr, nullptr, nullptr, nullptr, Qb, nullptr, nullptr);

    // ---- per bank ----
    for (int t = 0; t < 2; ++t) {
        const float* bank = t ? Fvt : Fvs;
        f2b(bank, xb, Nq * Dq);
        tc(xb,  W1b, Nq, Pq, Dq, MODE_BNRELU, 1.f, b1, g1, be1, m1, v1,
           nullptr, nullptr, H1b, nullptr, nullptr, nullptr);
        tc(H1b, W2b, Nq, Pq, Pq, MODE_BNRELU, 1.f, b2, g2, be2, m2, v2,
           nullptr, nullptr, H2b, nullptr, nullptr, nullptr);
        tc(H2b, W3b, Nq, 3 * Dq, Pq, MODE_QKV, 1.f, b3, nullptr, nullptr, nullptr,
           nullptr, nullptr, nullptr, nullptr, nullptr, Kb, Vb);

        // V^T for the A@V GEMM
        transpose_bf16<<<dim3(Dq / 32, Nq / 32), dim3(32, 8)>>>(Vb, Vt, Nq, Dq);

        // S = 0.1 * Q @ K^T   (bf16 out)
        tc(Qb, Kb, Bq, Nq, Dq, MODE_SMUL, 0.1f, nullptr, nullptr, nullptr,
           nullptr, nullptr, nullptr, nullptr, Sb, nullptr, nullptr, nullptr);
        softmax_bf16<<<Bq, 256>>>(Sb);

        // AV^T(d,b) = Vt @ S^T
        tc(Vt, Sb, Dq, Bq, Nq, MODE_SMUL, 1.f, nullptr, nullptr, nullptr,
           nullptr, nullptr, nullptr, nullptr, AVt, nullptr, nullptr, nullptr);
        transpose_bf16<<<dim3(Bq / 32, Dq / 32), dim3(32, 8)>>>(AVt, AVb, Dq, Bq);

        // F = Fv + AV @ Wp^T + bp   (fp32)
        tc(AVb, Wpb, Bq, Dq, Dq, MODE_RESID, 1.f, bp, nullptr, nullptr,
           nullptr, nullptr, Fv, nullptr, F, nullptr, nullptr, nullptr);

        norm_acc_kernel<<<Bq, 256>>>(F, G, t);
    }

    // ---- logits = exp(ls) * G @ Ft^T via bf16 split (3-term) ----
    build_Ap_kernel<<<(Bq * Dq + 255) / 256, 256>>>(G, Ap);
    build_Bp_kernel<<<(Cq * Dq + 255) / 256, 256>>>(Ft, Bp);
    tc(Ap, Bp, Bq, Cq, 3 * Dq, MODE_LS, 1.f, nullptr, nullptr, nullptr,
       nullptr, nullptr, nullptr, ls, out, nullptr, nullptr, nullptr);
}

// round 8
// speedup vs baseline: 7.9238x; 1.1507x over previous
#include <cuda_runtime.h>
#include <cuda_bf16.h>
#include <math.h>
#include <stdint.h>

typedef __nv_bfloat16 bf16;

#define Dq 1024
#define Pq 128
#define Bq 4096
#define Nq 8192
#define Cq 1000

// ---------------- scratch (static device memory; no allocations) -----------
__device__ bf16  g_xb [Nq * Dq];
__device__ bf16  g_W1b[Pq * Dq];
__device__ bf16  g_W2b[Pq * Pq];
__device__ bf16  g_W3b[3 * Dq * Pq];
__device__ bf16  g_Wpb[Dq * Dq];
__device__ bf16  g_H1b[Nq * Pq];
__device__ bf16  g_H2b[Nq * Pq];
__device__ bf16  g_Qb [Bq * Dq];
__device__ bf16  g_Kb [Nq * Dq];
__device__ bf16  g_Vb [Nq * Dq];
__device__ bf16  g_Sb [(size_t)Bq * Nq];
__device__ bf16  g_AVb[Bq * Dq];
__device__ float g_F  [Bq * Dq];
__device__ float g_G  [Bq * Dq];
__device__ bf16  g_Ap [(size_t)Bq * 3 * Dq];
__device__ bf16  g_Bp [(size_t)Cq * 3 * Dq];

// ---------------- helpers ---------------------------------------------------
__device__ __forceinline__ uint32_t s2u(const void* p) {
    uint32_t a;
    asm("{ .reg .u64 t; cvta.to.shared.u64 t, %1; cvt.u32.u64 %0, t; }"
        : "=r"(a) : "l"(p));
    return a;
}
__device__ __forceinline__ void ldmx4(uint32_t* r, uint32_t a) {
    asm volatile("ldmatrix.sync.aligned.m8n8.x4.shared.b16 {%0,%1,%2,%3}, [%4];"
                 : "=r"(r[0]), "=r"(r[1]), "=r"(r[2]), "=r"(r[3]) : "r"(a));
}
__device__ __forceinline__ void ldmx4t(uint32_t* r, uint32_t a) {
    asm volatile("ldmatrix.sync.aligned.m8n8.x4.trans.shared.b16 {%0,%1,%2,%3}, [%4];"
                 : "=r"(r[0]), "=r"(r[1]), "=r"(r[2]), "=r"(r[3]) : "r"(a));
}
__device__ __forceinline__ void mma16816(float* c, const uint32_t* a, const uint32_t* b) {
    asm volatile("mma.sync.aligned.m16n8k16.row.col.f32.bf16.bf16.f32 "
                 "{%0,%1,%2,%3}, {%4,%5,%6,%7}, {%8,%9}, {%0,%1,%2,%3};"
                 : "+f"(c[0]), "+f"(c[1]), "+f"(c[2]), "+f"(c[3])
                 : "r"(a[0]), "r"(a[1]), "r"(a[2]), "r"(a[3]),
                   "r"(b[0]), "r"(b[1]));
}
__device__ __forceinline__ void cp16(uint32_t dst, const void* src) {
    asm volatile("cp.async.cg.shared.global [%0], [%1], 16;"
                 :: "r"(dst), "l"(src));
}
__device__ __forceinline__ void cp16z(uint32_t dst, const void* src, int sz) {
    asm volatile("cp.async.cg.shared.global [%0], [%1], 16, %2;"
                 :: "r"(dst), "l"(src), "r"(sz));
}
__device__ __forceinline__ void cp_commit() {
    asm volatile("cp.async.commit_group;" ::: "memory");
}

// ---------------- mma.sync GEMM -----------------------------------
// TRANSB=true : C(MxN) = A(MxK) @ B(NxK)^T   (B row-major N x K)
// TRANSB=false: C(MxN) = A(MxK) @ B(KxN)     (B row-major K x N)
// BM=128, BN in {128,256}, BK=32, 2*BN threads, 3-stage cp.async.
#define SROW 80                         // A smem row stride (32 bf16 + pad)
#define ATILE_B (128 * SROW)            // 10240
#define NSTAGE  3

#define MODE_SMUL   0  // bf16 out = acc*scale
#define MODE_BNRELU 1  // bf16 out = relu(bn(acc+bias))
#define MODE_QKV    2  // grouped scatter (W3 rows pre-permuted), null dst skipped
#define MODE_RESID  3  // f32 out = acc + bias[c] + resid[row,c]
#define MODE_LS     4  // f32 out = acc * exp(*lsp), ragged-N guarded

template <int BN, bool TRANSB>
__device__ __forceinline__ void stage_load(const bf16* __restrict__ A,
                                           const bf16* __restrict__ Bm,
                                           int N_, int K_, int m0, int n0, int k0,
                                           uint32_t sbase, int tid)
{
    const int T = 2 * BN;
    // A: 512 16B chunks (128 rows x 4)
#pragma unroll
    for (int i = tid; i < 512; i += T) {
        const int row = i >> 2, ch = i & 3;
        cp16(sbase + row * SROW + ch * 16,
             A + (size_t)(m0 + row) * K_ + k0 + ch * 8);
    }
    if (TRANSB) {
        // B tile: BN rows (n) x 32 k, ragged-N guarded
#pragma unroll
        for (int i = tid; i < 4 * BN; i += T) {
            const int row = i >> 2, ch = i & 3;
            const int grow = n0 + row;
            const int v = (grow < N_);
            cp16z(sbase + ATILE_B + row * SROW + ch * 16,
                  Bm + (size_t)(v ? grow : 0) * K_ + n0 * 0 + k0 + ch * 8, v ? 16 : 0);
        }
    } else {
        // B tile: 32 rows (k) x BN n-cols; requires N_ % BN == 0
        constexpr int CPR = BN / 8;          // 16B chunks per row
        constexpr int BROW = 2 * BN + 16;
#pragma unroll
        for (int i = tid; i < 32 * CPR; i += T) {
            const int kk = i / CPR, ch = i % CPR;
            cp16(sbase + ATILE_B + kk * BROW + ch * 16,
                 Bm + (size_t)(k0 + kk) * N_ + n0 + ch * 8);
        }
    }
}

template <int BN, bool TRANSB>
__device__ __forceinline__ void compute_stage(uint32_t sbase, int lane,
                                              int wm, int wn,
                                              float acc[4][4][4])
{
    constexpr int BROW = 2 * BN + 16;
    const uint32_t aBase = sbase + (wm * 64 + (lane & 15)) * SROW + (lane >> 4) * 16;
    uint32_t bBase;
    if (TRANSB) {
        bBase = sbase + ATILE_B +
                (wn * 32 + ((lane >> 4) << 3) + (lane & 7)) * SROW +
                (((lane >> 3) & 1) << 4);
    } else {
        // lanes 0-7: rows k0-7 @ n-base; 8-15: k8-15 @ n-base; 16-23: k0-7 @ n+8; 24-31: k8-15 @ n+8
        bBase = sbase + ATILE_B +
                ((lane & 7) + (((lane >> 3) & 1) << 3)) * BROW +
                (wn * 32 + (lane >> 4) * 8) * 2;
    }
#pragma unroll
    for (int kh = 0; kh < 2; ++kh) {
        uint32_t af[4][4];
#pragma unroll
        for (int tm = 0; tm < 4; ++tm)
            ldmx4(af[tm], aBase + tm * 16 * SROW + kh * 32);
        uint32_t bfr[4][2];
        if (TRANSB) {
#pragma unroll
            for (int tp = 0; tp < 2; ++tp) {
                uint32_t r[4];
                ldmx4(r, bBase + tp * 16 * SROW + kh * 32);
                bfr[2 * tp][0] = r[0];  bfr[2 * tp][1] = r[1];
                bfr[2 * tp + 1][0] = r[2]; bfr[2 * tp + 1][1] = r[3];
            }
        } else {
#pragma unroll
            for (int tp = 0; tp < 2; ++tp) {
                uint32_t r[4];
                ldmx4t(r, bBase + kh * 16 * BROW + tp * 32);
                bfr[2 * tp][0] = r[0];  bfr[2 * tp][1] = r[1];
                bfr[2 * tp + 1][0] = r[2]; bfr[2 * tp + 1][1] = r[3];
            }
        }
#pragma unroll
        for (int tm = 0; tm < 4; ++tm)
#pragma unroll
            for (int tn = 0; tn < 4; ++tn)
                mma16816(acc[tm][tn], af[tm], bfr[tn]);
    }
}

template <int BN, bool TRANSB>
__global__ __launch_bounds__(2 * BN)
void tc_gemm(const bf16* __restrict__ A, const bf16* __restrict__ Bm,
             int M, int N, int K, int mode, float scale,
             const float* __restrict__ bias, const float* __restrict__ gam,
             const float* __restrict__ bet, const float* __restrict__ mean,
             const float* __restrict__ var, const float* __restrict__ resid,
             const float* __restrict__ lsp,
             void* __restrict__ Cout,
             bf16* __restrict__ qo, bf16* __restrict__ ko, bf16* __restrict__ vo)
{
    constexpr int NW = BN / 32;
    constexpr int BSTAGE = TRANSB ? BN * SROW : 32 * (2 * BN + 16);
    constexpr int STAGE = ATILE_B + BSTAGE;
    extern __shared__ char smem[];
    const uint32_t sb = s2u(smem);
    const int tid  = threadIdx.x;
    const int lane = tid & 31;
    const int wid  = tid >> 5;
    const int wm = wid / NW, wn = wid % NW;
    const int m0 = blockIdx.y * 128;
    const int n0 = blockIdx.x * BN;
    const int NC = K >> 5;

    float acc[4][4][4];
#pragma unroll
    for (int a = 0; a < 4; ++a)
#pragma unroll
        for (int b = 0; b < 4; ++b)
#pragma unroll
            for (int c = 0; c < 4; ++c) acc[a][b][c] = 0.f;

#pragma unroll
    for (int s = 0; s < 2; ++s) {
        stage_load<BN, TRANSB>(A, Bm, N, K, m0, n0, s * 32, sb + s * STAGE, tid);
        cp_commit();
    }

    for (int i = 0; i < NC; ++i) {
        asm volatile("cp.async.wait_group 1;" ::: "memory");
        __syncthreads();
        compute_stage<BN, TRANSB>(sb + (i % NSTAGE) * STAGE, lane, wm, wn, acc);
        if (i + 2 < NC)
            stage_load<BN, TRANSB>(A, Bm, N, K, m0, n0, (i + 2) * 32,
                                   sb + ((i + 2) % NSTAGE) * STAGE, tid);
        cp_commit();
    }
    asm volatile("cp.async.wait_group 0;" ::: "memory");

    // ---------------- epilogue ---------------------------------------------
    const float lsv = (mode == MODE_LS) ? __expf(lsp[0]) : 1.f;

#pragma unroll
    for (int tm = 0; tm < 4; ++tm) {
#pragma unroll
        for (int tn = 0; tn < 4; ++tn) {
            const int r0 = m0 + wm * 64 + tm * 16 + (lane >> 2);
            const int c0 = n0 + wn * 32 + tn * 8 + 2 * (lane & 3);
#pragma unroll
            for (int h = 0; h < 2; ++h) {
                const int row = r0 + 8 * h;
                const float f0 = acc[tm][tn][2 * h];
                const float f1 = acc[tm][tn][2 * h + 1];
                if (mode == MODE_SMUL) {
                    __nv_bfloat162 p = __floats2bfloat162_rn(f0 * scale, f1 * scale);
                    *reinterpret_cast<__nv_bfloat162*>(
                        (bf16*)Cout + (size_t)row * N + c0) = p;
                } else if (mode == MODE_BNRELU) {
                    float x0 = f0 + bias[c0];
                    x0 = (x0 - mean[c0]) * rsqrtf(var[c0] + 1e-5f) * gam[c0] + bet[c0];
                    float x1 = f1 + bias[c0 + 1];
                    x1 = (x1 - mean[c0 + 1]) * rsqrtf(var[c0 + 1] + 1e-5f) * gam[c0 + 1]
                         + bet[c0 + 1];
                    __nv_bfloat162 p = __floats2bfloat162_rn(fmaxf(x0, 0.f),
                                                             fmaxf(x1, 0.f));
                    *reinterpret_cast<__nv_bfloat162*>(
                        (bf16*)Cout + (size_t)row * N + c0) = p;
                } else if (mode == MODE_QKV) {
                    // cols pre-grouped: [0,1024) q, [1024,2048) k, [2048,3072) v
                    const int g = c0 >> 10;
                    const int d = c0 & 1023;
                    bf16* dst = (g == 0) ? qo : ((g == 1) ? ko : vo);
                    if (dst) {
                        const float hv0 = f0 + bias[3 * d + g];
                        const float hv1 = f1 + bias[3 * (d + 1) + g];
                        __nv_bfloat162 p = __floats2bfloat162_rn(hv0, hv1);
                        *reinterpret_cast<__nv_bfloat162*>(
                            dst + (size_t)row * 1024 + d) = p;
                    }
                } else if (mode == MODE_RESID) {
                    float* Cf = (float*)Cout + (size_t)row * N + c0;
                    const float2 rv = *reinterpret_cast<const float2*>(
                        resid + (size_t)row * N + c0);
                    float2 o;
                    o.x = f0 + bias[c0] + rv.x;
                    o.y = f1 + bias[c0 + 1] + rv.y;
                    *reinterpret_cast<float2*>(Cf) = o;
                } else { // MODE_LS (N ragged; N even so pair-guard ok)
                    if (c0 < N) {
                        float* Cf = (float*)Cout + (size_t)row * N + c0;
                        Cf[0] = f0 * lsv;
                        Cf[1] = f1 * lsv;
                    }
                }
            }
        }
    }
}

#define SMEM_NT128 (NSTAGE * (ATILE_B + 128 * SROW))        // 61440
#define SMEM_NT256 (NSTAGE * (ATILE_B + 256 * SROW))        // 92160
#define SMEM_NN256 (NSTAGE * (ATILE_B + 32 * (2 * 256 + 16)))  // 81408

// ---------------- small kernels --------------------------------------------
__global__ void f2b_kernel(const float* __restrict__ in, bf16* __restrict__ out, int n)
{
    const int i = (blockIdx.x * blockDim.x + threadIdx.x) * 4;
    if (i < n) {
        const float4 v = *reinterpret_cast<const float4*>(in + i);
        __nv_bfloat162 a = __floats2bfloat162_rn(v.x, v.y);
        __nv_bfloat162 b = __floats2bfloat162_rn(v.z, v.w);
        uint2 pk;
        pk.x = *reinterpret_cast<uint32_t*>(&a);
        pk.y = *reinterpret_cast<uint32_t*>(&b);
        *reinterpret_cast<uint2*>(out + i) = pk;
    }
}

// W3 (3072,128) -> bf16 with rows permuted: out row g*1024+d = orig row 3d+g
__global__ void f2bW3_kernel(const float* __restrict__ in, bf16* __restrict__ out)
{
    const int idx = blockIdx.x * blockDim.x + threadIdx.x;
    if (idx >= 3072 * 128) return;
    const int rp = idx >> 7, c = idx & 127;
    const int g = rp >> 10, d = rp & 1023;
    out[idx] = __float2bfloat16(in[(3 * d + g) * 128 + c]);
}

// in-place row softmax over 8192 bf16 cols
__global__ void softmax_bf16(bf16* __restrict__ S)
{
    bf16* p = S + (size_t)blockIdx.x * 8192;
    const int tid = threadIdx.x;
    const int lane = tid & 31, w = tid >> 5;

    float v[32];
    float mx = -3.4e38f;
#pragma unroll
    for (int i = 0; i < 16; ++i) {
        const __nv_bfloat162 h2 = *reinterpret_cast<const __nv_bfloat162*>(
            p + tid * 2 + (i << 9));
        const float2 f2 = __bfloat1622float2(h2);
        v[2 * i] = f2.x; v[2 * i + 1] = f2.y;
        mx = fmaxf(mx, fmaxf(f2.x, f2.y));
    }
    __shared__ float shm[8], shs[8];
#pragma unroll
    for (int o = 16; o > 0; o >>= 1) mx = fmaxf(mx, __shfl_xor_sync(0xffffffffu, mx, o));
    if (lane == 0) shm[w] = mx;
    __syncthreads();
    if (tid == 0) {
        float m = shm[0];
#pragma unroll
        for (int i = 1; i < 8; ++i) m = fmaxf(m, shm[i]);
        shm[0] = m;
    }
    __syncthreads();
    mx = shm[0];

    float s = 0.f;
#pragma unroll
    for (int i = 0; i < 32; ++i) { v[i] = __expf(v[i] - mx); s += v[i]; }
#pragma unroll
    for (int o = 16; o > 0; o >>= 1) s += __shfl_xor_sync(0xffffffffu, s, o);
    if (lane == 0) shs[w] = s;
    __syncthreads();
    if (tid == 0) {
        float t = 0.f;
#pragma unroll
        for (int i = 0; i < 8; ++i) t += shs[i];
        shs[0] = t;
    }
    __syncthreads();
    const float inv = 1.f / shs[0];
#pragma unroll
    for (int i = 0; i < 16; ++i) {
        const __nv_bfloat162 h2 = __floats2bfloat162_rn(v[2 * i] * inv,
                                                        v[2 * i + 1] * inv);
        *reinterpret_cast<__nv_bfloat162*>(p + tid * 2 + (i << 9)) = h2;
    }
}

// row L2-normalize (D=1024) F -> accumulate into G
__global__ void norm_acc_kernel(const float* __restrict__ F, float* __restrict__ G,
                                int accumulate)
{
    const float* p = F + (size_t)blockIdx.x * 1024;
    float* q = G + (size_t)blockIdx.x * 1024;
    const int tid = threadIdx.x;
    const int lane = tid & 31, w = tid >> 5;

    const float4 v = *reinterpret_cast<const float4*>(p + tid * 4);
    float ss = v.x * v.x + v.y * v.y + v.z * v.z + v.w * v.w;
#pragma unroll
    for (int o = 16; o > 0; o >>= 1) ss += __shfl_xor_sync(0xffffffffu, ss, o);
    __shared__ float sh[8];
    if (lane == 0) sh[w] = ss;
    __syncthreads();
    if (tid == 0) {
        float t = 0.f;
#pragma unroll
        for (int i = 0; i < 8; ++i) t += sh[i];
        sh[0] = t;
    }
    __syncthreads();
    const float rn = rsqrtf(sh[0]);

    float4 o;
    if (accumulate) {
        const float4 g0 = *reinterpret_cast<const float4*>(q + tid * 4);
        o = make_float4(g0.x + v.x * rn, g0.y + v.y * rn,
                        g0.z + v.z * rn, g0.w + v.w * rn);
    } else {
        o = make_float4(v.x * rn, v.y * rn, v.z * rn, v.w * rn);
    }
    *reinterpret_cast<float4*>(q + tid * 4) = o;
}

// A' = [Gh | Gh | Gl]  (Bq x 3D)
__global__ void build_Ap_kernel(const float* __restrict__ G, bf16* __restrict__ Ap)
{
    const int idx = blockIdx.x * blockDim.x + threadIdx.x;
    if (idx >= Bq * Dq) return;
    const int r = idx >> 10, c = idx & 1023;
    const float v = G[idx];
    const bf16 h = __float2bfloat16(v);
    const bf16 l = __float2bfloat16(v - __bfloat162float(h));
    bf16* row = Ap + (size_t)r * 3072;
    row[c] = h; row[1024 + c] = h; row[2048 + c] = l;
}

// B' = [Fh | Fl | Fh]  (Cq x 3D)
__global__ void build_Bp_kernel(const float* __restrict__ Ft, bf16* __restrict__ Bp)
{
    const int idx = blockIdx.x * blockDim.x + threadIdx.x;
    if (idx >= Cq * Dq) return;
    const int r = idx >> 10, c = idx & 1023;
    const float v = Ft[idx];
    const bf16 h = __float2bfloat16(v);
    const bf16 l = __float2bfloat16(v - __bfloat162float(h));
    bf16* row = Bp + (size_t)r * 3072;
    row[c] = h; row[1024 + c] = l; row[2048 + c] = h;
}

// ---------------- host side ------------------------------------------------
static void tc(bool transB, const bf16* A, const bf16* B, int M, int N, int K,
               int mode, float scale,
               const float* bias, const float* gam, const float* bet,
               const float* mean, const float* var, const float* resid,
               const float* lsp, void* C, bf16* qo, bf16* ko, bf16* vo)
{
    if (!transB) {
        dim3 grid(N / 256, M / 128);
        tc_gemm<256, false><<<grid, 512, SMEM_NN256>>>(A, B, M, N, K, mode, scale,
            bias, gam, bet, mean, var, resid, lsp, C, qo, ko, vo);
    } else if (N >= 256) {
        dim3 grid((N + 255) / 256, M / 128);
        tc_gemm<256, true><<<grid, 512, SMEM_NT256>>>(A, B, M, N, K, mode, scale,
            bias, gam, bet, mean, var, resid, lsp, C, qo, ko, vo);
    } else {
        dim3 grid((N + 127) / 128, M / 128);
        tc_gemm<128, true><<<grid, 256, SMEM_NT128>>>(A, B, M, N, K, mode, scale,
            bias, gam, bet, mean, var, resid, lsp, C, qo, ko, vo);
    }
}

static void f2b(const float* in, bf16* out, int n)
{
    f2b_kernel<<<(n / 4 + 255) / 256, 256>>>(in, out, n);
}

extern "C" void kernel_launch(void* const* d_in, const int* in_sizes, int n_in,
                              void* d_out, int out_size)
{
    (void)in_sizes; (void)n_in; (void)out_size;
    const float* Ft  = (const float*)d_in[0];
    const float* Fv  = (const float*)d_in[1];
    const float* Fvs = (const float*)d_in[2];
    const float* Fvt = (const float*)d_in[3];
    const float* W1  = (const float*)d_in[4];
    const float* b1  = (const float*)d_in[5];
    const float* g1  = (const float*)d_in[6];
    const float* be1 = (const float*)d_in[7];
    const float* m1  = (const float*)d_in[8];
    const float* v1  = (const float*)d_in[9];
    const float* W2  = (const float*)d_in[10];
    const float* b2  = (const float*)d_in[11];
    const float* g2  = (const float*)d_in[12];
    const float* be2 = (const float*)d_in[13];
    const float* m2  = (const float*)d_in[14];
    const float* v2  = (const float*)d_in[15];
    const float* W3  = (const float*)d_in[16];
    const float* b3  = (const float*)d_in[17];
    const float* Wp  = (const float*)d_in[18];
    const float* bp  = (const float*)d_in[19];
    const float* ls  = (const float*)d_in[20];
    float* out = (float*)d_out;

    cudaFuncSetAttribute((const void*)tc_gemm<128, true>,
                         cudaFuncAttributeMaxDynamicSharedMemorySize, SMEM_NT128);
    cudaFuncSetAttribute((const void*)tc_gemm<256, true>,
                         cudaFuncAttributeMaxDynamicSharedMemorySize, SMEM_NT256);
    cudaFuncSetAttribute((const void*)tc_gemm<256, false>,
                         cudaFuncAttributeMaxDynamicSharedMemorySize, SMEM_NN256);

    bf16 *xb, *W1b, *W2b, *W3b, *Wpb, *H1b, *H2b, *Qb, *Kb, *Vb, *Sb, *AVb, *Ap, *Bp;
    float *F, *G;
    cudaGetSymbolAddress((void**)&xb,  g_xb);
    cudaGetSymbolAddress((void**)&W1b, g_W1b);
    cudaGetSymbolAddress((void**)&W2b, g_W2b);
    cudaGetSymbolAddress((void**)&W3b, g_W3b);
    cudaGetSymbolAddress((void**)&Wpb, g_Wpb);
    cudaGetSymbolAddress((void**)&H1b, g_H1b);
    cudaGetSymbolAddress((void**)&H2b, g_H2b);
    cudaGetSymbolAddress((void**)&Qb,  g_Qb);
    cudaGetSymbolAddress((void**)&Kb,  g_Kb);
    cudaGetSymbolAddress((void**)&Vb,  g_Vb);
    cudaGetSymbolAddress((void**)&Sb,  g_Sb);
    cudaGetSymbolAddress((void**)&AVb, g_AVb);
    cudaGetSymbolAddress((void**)&F,   g_F);
    cudaGetSymbolAddress((void**)&G,   g_G);
    cudaGetSymbolAddress((void**)&Ap,  g_Ap);
    cudaGetSymbolAddress((void**)&Bp,  g_Bp);

    // weight conversions (W3 row-permuted for grouped qkv epilogue)
    f2b(W1, W1b, Pq * Dq);
    f2b(W2, W2b, Pq * Pq);
    f2bW3_kernel<<<(3072 * 128 + 255) / 256, 256>>>(W3, W3b);
    f2b(Wp, Wpb, Dq * Dq);

    // ---- pre_project(Fv) -> Q ----
    f2b(Fv, xb, Bq * Dq);
    tc(true, xb,  W1b, Bq, Pq, Dq, MODE_BNRELU, 1.f, b1, g1, be1, m1, v1,
       nullptr, nullptr, H1b, nullptr, nullptr, nullptr);
    tc(true, H1b, W2b, Bq, Pq, Pq, MODE_BNRELU, 1.f, b2, g2, be2, m2, v2,
       nullptr, nullptr, H2b, nullptr, nullptr, nullptr);
    tc(true, H2b, W3b, Bq, 3 * Dq, Pq, MODE_QKV, 1.f, b3, nullptr, nullptr, nullptr,
       nullptr, nullptr, nullptr, nullptr, Qb, nullptr, nullptr);

    // ---- per bank ----
    for (int t = 0; t < 2; ++t) {
        const float* bank = t ? Fvt : Fvs;
        f2b(bank, xb, Nq * Dq);
        tc(true, xb,  W1b, Nq, Pq, Dq, MODE_BNRELU, 1.f, b1, g1, be1, m1, v1,
           nullptr, nullptr, H1b, nullptr, nullptr, nullptr);
        tc(true, H1b, W2b, Nq, Pq, Pq, MODE_BNRELU, 1.f, b2, g2, be2, m2, v2,
           nullptr, nullptr, H2b, nullptr, nullptr, nullptr);
        tc(true, H2b, W3b, Nq, 3 * Dq, Pq, MODE_QKV, 1.f, b3, nullptr, nullptr,
           nullptr, nullptr, nullptr, nullptr, nullptr, nullptr, Kb, Vb);

        // S = 0.1 * Q @ K^T   (bf16 out)
        tc(true, Qb, Kb, Bq, Nq, Dq, MODE_SMUL, 0.1f, nullptr, nullptr, nullptr,
           nullptr, nullptr, nullptr, nullptr, Sb, nullptr, nullptr, nullptr);
        softmax_bf16<<<Bq, 256>>>(Sb);

        // AV = S @ V  (NN: V is (K=8192, N=1024) row-major)
        tc(false, Sb, Vb, Bq, Dq, Nq, MODE_SMUL, 1.f, nullptr, nullptr, nullptr,
           nullptr, nullptr, nullptr, nullptr, AVb, nullptr, nullptr, nullptr);

        // F = Fv + AV @ Wp^T + bp   (fp32)
        tc(true, AVb, Wpb, Bq, Dq, Dq, MODE_RESID, 1.f, bp, nullptr, nullptr,
           nullptr, nullptr, Fv, nullptr, F, nullptr, nullptr, nullptr);

        norm_acc_kernel<<<Bq, 256>>>(F, G, t);
    }

    // ---- logits = exp(ls) * G @ Ft^T via bf16 split (3-term) ----
    build_Ap_kernel<<<(Bq * Dq + 255) / 256, 256>>>(G, Ap);
    build_Bp_kernel<<<(Cq * Dq + 255) / 256, 256>>>(Ft, Bp);
    tc(true, Ap, Bp, Bq, Cq, 3 * Dq, MODE_LS, 1.f, nullptr, nullptr, nullptr,
       nullptr, nullptr, nullptr, ls, out, nullptr, nullptr, nullptr);
}